// round 1
// baseline (speedup 1.0000x reference)
#include <cuda_runtime.h>
#include <cuda_bf16.h>
#include <stdint.h>

// Problem constants (shapes are fixed by the dataset)
#define MAX_N 50000
#define MAX_E 800000
#define HD    256   // hidden dim

// ---------------- scratch (no allocations allowed) ----------------
__device__ int   g_deg[MAX_N];
__device__ int   g_rowptr[MAX_N + 1];
__device__ int   g_cursor[MAX_N];
__device__ int   g_esrc[MAX_E];
__device__ float g_dinv[MAX_N];
__device__ float g_agg[(size_t)MAX_N * HD];
__device__ float g_h[(size_t)MAX_N * HD];

// ---------------- setup kernels ----------------
__global__ void zero_deg_kernel(int n) {
    int i = blockIdx.x * blockDim.x + threadIdx.x;
    if (i < n) g_deg[i] = 0;
}

__global__ void hist_kernel(const int* __restrict__ ei, int e) {
    int i = blockIdx.x * blockDim.x + threadIdx.x;
    if (i < e) {
        int dst = ei[e + i];   // edge_index[1, i]
        atomicAdd(&g_deg[dst], 1);
    }
}

// Single-block exclusive scan over g_deg -> g_rowptr / g_cursor, plus dinv.
__global__ void scan_kernel(int n) {
    __shared__ int sh[1024];
    __shared__ int s_off;
    int tid = threadIdx.x;
    if (tid == 0) s_off = 0;
    __syncthreads();
    for (int base = 0; base < n; base += 1024) {
        int i = base + tid;
        int v = (i < n) ? g_deg[i] : 0;
        if (i < n) g_dinv[i] = rsqrtf((float)(v + 1));  // +1 = self loop
        sh[tid] = v;
        __syncthreads();
        // Hillis-Steele inclusive scan
        #pragma unroll
        for (int d = 1; d < 1024; d <<= 1) {
            int t = (tid >= d) ? sh[tid - d] : 0;
            __syncthreads();
            sh[tid] += t;
            __syncthreads();
        }
        int total = sh[1023];
        int excl  = sh[tid] - v;
        int r = s_off + excl;
        if (i < n) { g_rowptr[i] = r; g_cursor[i] = r; }
        __syncthreads();
        if (tid == 0) s_off += total;
        __syncthreads();
    }
    if (tid == 0) g_rowptr[n] = s_off;
}

__global__ void fill_kernel(const int* __restrict__ ei, int e) {
    int i = blockIdx.x * blockDim.x + threadIdx.x;
    if (i < e) {
        int src = ei[i];
        int dst = ei[e + i];
        int pos = atomicAdd(&g_cursor[dst], 1);
        g_esrc[pos] = src;
    }
}

// ---------------- aggregation: one warp per node, gather formulation ------
// out[i] = dinv[i] * ( dinv[i]*x[i] + sum_{s in nbrs(i)} dinv[s]*x[s] )
template <int F>   // F = row width in floats (128 or 256)
__global__ void agg_kernel(const float* __restrict__ x, float* __restrict__ out, int n) {
    int warp = blockIdx.x * (blockDim.x >> 5) + (threadIdx.x >> 5);
    int lane = threadIdx.x & 31;
    if (warp >= n) return;
    constexpr int V = F / 128;  // float4 per lane
    const float4* __restrict__ x4 = (const float4*)x;
    float di = g_dinv[warp];
    float4 acc[V];
    #pragma unroll
    for (int v = 0; v < V; v++) {
        float4 t = x4[(size_t)warp * (F / 4) + v * 32 + lane];
        acc[v].x = di * t.x; acc[v].y = di * t.y;
        acc[v].z = di * t.z; acc[v].w = di * t.w;
    }
    int beg = g_rowptr[warp], end = g_rowptr[warp + 1];
    for (int e = beg; e < end; e++) {
        int s = g_esrc[e];
        float w = g_dinv[s];
        #pragma unroll
        for (int v = 0; v < V; v++) {
            float4 t = x4[(size_t)s * (F / 4) + v * 32 + lane];
            acc[v].x = fmaf(w, t.x, acc[v].x);
            acc[v].y = fmaf(w, t.y, acc[v].y);
            acc[v].z = fmaf(w, t.z, acc[v].z);
            acc[v].w = fmaf(w, t.w, acc[v].w);
        }
    }
    float4* __restrict__ o4 = (float4*)out;
    #pragma unroll
    for (int v = 0; v < V; v++) {
        float4 r;
        r.x = di * acc[v].x; r.y = di * acc[v].y;
        r.z = di * acc[v].z; r.w = di * acc[v].w;
        o4[(size_t)warp * (F / 4) + v * 32 + lane] = r;
    }
}

// ---------------- GEMM + bias + relu: C[M,256] = relu(A[M,K] @ W[K,256] + b)
// 64x256 block tile, 16 k-step, 256 threads, 8x8 per-thread microtile.
template <int K>
__global__ __launch_bounds__(256)
void gemm_bias_relu(const float* __restrict__ A, const float* __restrict__ W,
                    const float* __restrict__ bias, float* __restrict__ C, int M) {
    __shared__ float As[64][16];
    __shared__ float Bs[16][256];
    const int tid  = threadIdx.x;
    const int row0 = blockIdx.x * 64;
    const int trow = tid >> 5;   // 0..7  (uniform per warp -> broadcast A reads)
    const int tcol = tid & 31;   // 0..31 (cols tcol + 32*j, conflict-free B reads)

    float acc[8][8];
    #pragma unroll
    for (int r = 0; r < 8; r++)
        #pragma unroll
        for (int j = 0; j < 8; j++) acc[r][j] = 0.f;

    const int ar = tid >> 2;        // 0..63
    const int ac = (tid & 3) * 4;   // 0,4,8,12

    for (int k0 = 0; k0 < K; k0 += 16) {
        float4 av = make_float4(0.f, 0.f, 0.f, 0.f);
        if (row0 + ar < M)
            av = *(const float4*)(A + (size_t)(row0 + ar) * K + k0 + ac);
        *(float4*)&As[ar][ac] = av;
        #pragma unroll
        for (int t = 0; t < 4; t++) {
            int j  = tid + t * 256;       // 0..1023
            int kr = j >> 6;              // 0..15
            int cg = (j & 63) * 4;        // 0..252
            *(float4*)&Bs[kr][cg] = *(const float4*)(W + (size_t)(k0 + kr) * 256 + cg);
        }
        __syncthreads();
        #pragma unroll
        for (int k = 0; k < 16; k++) {
            float a[8], b[8];
            #pragma unroll
            for (int r = 0; r < 8; r++) a[r] = As[trow * 8 + r][k];
            #pragma unroll
            for (int j = 0; j < 8; j++) b[j] = Bs[k][tcol + 32 * j];
            #pragma unroll
            for (int r = 0; r < 8; r++)
                #pragma unroll
                for (int j = 0; j < 8; j++)
                    acc[r][j] = fmaf(a[r], b[j], acc[r][j]);
        }
        __syncthreads();
    }
    #pragma unroll
    for (int j = 0; j < 8; j++) {
        int col = tcol + 32 * j;
        float bb = bias[col];
        #pragma unroll
        for (int r = 0; r < 8; r++) {
            int row = row0 + trow * 8 + r;
            if (row < M) {
                float v = acc[r][j] + bb;
                C[(size_t)row * 256 + col] = v > 0.f ? v : 0.f;
            }
        }
    }
}

// ---------------- pooling + heads ----------------
__device__ __forceinline__ int lower_bound_i(const int* __restrict__ a, int n, int key) {
    int lo = 0, hi = n;
    while (lo < hi) {
        int mid = (lo + hi) >> 1;
        if (a[mid] < key) lo = mid + 1; else hi = mid;
    }
    return lo;
}

__global__ __launch_bounds__(256)
void pool_heads_kernel(const float* __restrict__ h, const int* __restrict__ batch,
                       const float* __restrict__ Wmu, const float* __restrict__ bmu,
                       const float* __restrict__ Wlv, const float* __restrict__ blv,
                       float* __restrict__ out, int n, int g_total) {
    int g = blockIdx.x;
    __shared__ float hg[256];
    int lo = lower_bound_i(batch, n, g);
    int hi = lower_bound_i(batch, n, g + 1);
    int tid = threadIdx.x;
    float s = 0.f;
    for (int i = lo; i < hi; i++) s += h[(size_t)i * 256 + tid];
    float cnt = (float)(hi - lo);
    hg[tid] = s / fmaxf(cnt, 1.0f);
    __syncthreads();
    if (tid < 64) {
        float m = bmu[tid];
        #pragma unroll 8
        for (int k = 0; k < 256; k++) m = fmaf(hg[k], Wmu[k * 64 + tid], m);
        out[g * 64 + tid] = m;
    } else if (tid < 128) {
        int t = tid - 64;
        float m = blv[t];
        #pragma unroll 8
        for (int k = 0; k < 256; k++) m = fmaf(hg[k], Wlv[k * 64 + t], m);
        out[(size_t)g_total * 64 + g * 64 + t] = m;
    }
}

// ---------------- launch ----------------
extern "C" void kernel_launch(void* const* d_in, const int* in_sizes, int n_in,
                              void* d_out, int out_size) {
    const float* x     = (const float*)d_in[0];
    const int*   ei    = (const int*)d_in[1];
    const int*   batch = (const int*)d_in[2];
    // num_graphs may or may not be materialized as an input; detect by count.
    int wi = (n_in >= 12) ? 4 : 3;
    const float* W1  = (const float*)d_in[wi + 0];
    const float* b1  = (const float*)d_in[wi + 1];
    const float* W2  = (const float*)d_in[wi + 2];
    const float* b2  = (const float*)d_in[wi + 3];
    const float* Wmu = (const float*)d_in[wi + 4];
    const float* bmu = (const float*)d_in[wi + 5];
    const float* Wlv = (const float*)d_in[wi + 6];
    const float* blv = (const float*)d_in[wi + 7];
    float* out = (float*)d_out;

    int n = in_sizes[0] / 128;           // nodes
    int e = in_sizes[1] / 2;             // edges
    int g = out_size / 128;              // graphs (out = 2 * G * 64)

    // scratch (device globals) — get raw pointers via symbol-bound kernels
    zero_deg_kernel<<<(n + 255) / 256, 256>>>(n);
    hist_kernel<<<(e + 255) / 256, 256>>>(ei, e);
    scan_kernel<<<1, 1024>>>(n);
    fill_kernel<<<(e + 255) / 256, 256>>>(ei, e);

    // access the global scratch through device symbols inside the kernels;
    // for the GEMM/agg kernels we need raw pointers -> use the known symbols.
    // (agg/gemm take pointers; g_agg/g_h are referenced via helper below)
    // Layer 1: agg(x) at width 128, then GEMM 128->256 + relu
    {
        // agg writes into g_agg (stride 128)
        extern __device__ float g_agg[];
        extern __device__ float g_h[];
    }
    // We cannot take device-symbol addresses on host without cudaGetSymbolAddress
    // (allowed: not an allocation). Do it once per launch; it's cheap & capturable-safe
    // (pure driver query, no stream ops).
    static float* p_agg = nullptr;
    static float* p_h   = nullptr;
    if (!p_agg) {
        cudaGetSymbolAddress((void**)&p_agg, g_agg);
        cudaGetSymbolAddress((void**)&p_h,   g_h);
    }

    agg_kernel<128><<<(n + 7) / 8, 256>>>(x, p_agg, n);
    gemm_bias_relu<128><<<(n + 63) / 64, 256>>>(p_agg, W1, b1, p_h, n);
    agg_kernel<256><<<(n + 7) / 8, 256>>>(p_h, p_agg, n);
    gemm_bias_relu<256><<<(n + 63) / 64, 256>>>(p_agg, W2, b2, p_h, n);
    pool_heads_kernel<<<g, 256>>>(p_h, batch, Wmu, bmu, Wlv, blv, out, n, g);
}

// round 3
// speedup vs baseline: 1.5118x; 1.5118x over previous
#include <cuda_runtime.h>
#include <cuda_bf16.h>
#include <stdint.h>

#define MAX_N 50000
#define MAX_E 800000
#define HD    256

// ---------------- scratch ----------------
__device__ int   g_deg[MAX_N];
__device__ int   g_rowptr[MAX_N + 1];
__device__ int   g_cursor[MAX_N];
__device__ int   g_esrc[MAX_E];
__device__ float g_dinv[MAX_N];
__device__ float g_agg[(size_t)MAX_N * HD];
__device__ float g_h[(size_t)MAX_N * HD];
// pre-transposed + bf16-split weights, layout [n][k] (col-major B for mma row.col)
__device__ __nv_bfloat16 g_W1h[256 * 128];
__device__ __nv_bfloat16 g_W1l[256 * 128];
__device__ __nv_bfloat16 g_W2h[256 * 256];
__device__ __nv_bfloat16 g_W2l[256 * 256];

// ---------------- setup kernels ----------------
__global__ void zero_deg_kernel(int n) {
    int i = blockIdx.x * blockDim.x + threadIdx.x;
    if (i < n) g_deg[i] = 0;
}
__global__ void hist_kernel(const int* __restrict__ ei, int e) {
    int i = blockIdx.x * blockDim.x + threadIdx.x;
    if (i < e) atomicAdd(&g_deg[ei[e + i]], 1);
}
__global__ void scan_kernel(int n) {
    __shared__ int sh[1024];
    __shared__ int s_off;
    int tid = threadIdx.x;
    if (tid == 0) s_off = 0;
    __syncthreads();
    for (int base = 0; base < n; base += 1024) {
        int i = base + tid;
        int v = (i < n) ? g_deg[i] : 0;
        if (i < n) g_dinv[i] = rsqrtf((float)(v + 1));
        sh[tid] = v;
        __syncthreads();
        #pragma unroll
        for (int d = 1; d < 1024; d <<= 1) {
            int t = (tid >= d) ? sh[tid - d] : 0;
            __syncthreads();
            sh[tid] += t;
            __syncthreads();
        }
        int total = sh[1023];
        int r = s_off + sh[tid] - v;
        if (i < n) { g_rowptr[i] = r; g_cursor[i] = r; }
        __syncthreads();
        if (tid == 0) s_off += total;
        __syncthreads();
    }
    if (tid == 0) g_rowptr[n] = s_off;
}
__global__ void fill_kernel(const int* __restrict__ ei, int e) {
    int i = blockIdx.x * blockDim.x + threadIdx.x;
    if (i < e) {
        int src = ei[i];
        int pos = atomicAdd(&g_cursor[ei[e + i]], 1);
        g_esrc[pos] = src;
    }
}

// transpose + bf16-split: Wh/Wl[n*K+k] from W[k*256+n]
template <int K>
__global__ void prep_w_kernel(const float* __restrict__ W, __nv_bfloat16* __restrict__ Wh,
                              __nv_bfloat16* __restrict__ Wl) {
    int i = blockIdx.x * blockDim.x + threadIdx.x;
    if (i < 256 * K) {
        int n = i / K, k = i % K;
        float w = W[k * 256 + n];
        __nv_bfloat16 h = __float2bfloat16_rn(w);
        Wh[i] = h;
        Wl[i] = __float2bfloat16_rn(w - __bfloat162float(h));
    }
}

// ---------------- aggregation (warp-per-node gather) ----------------
template <int F>
__global__ void agg_kernel(const float* __restrict__ x, float* __restrict__ out, int n) {
    int warp = blockIdx.x * (blockDim.x >> 5) + (threadIdx.x >> 5);
    int lane = threadIdx.x & 31;
    if (warp >= n) return;
    constexpr int V = F / 128;
    const float4* __restrict__ x4 = (const float4*)x;
    float di = g_dinv[warp];
    float4 acc[V];
    #pragma unroll
    for (int v = 0; v < V; v++) {
        float4 t = x4[(size_t)warp * (F / 4) + v * 32 + lane];
        acc[v].x = di * t.x; acc[v].y = di * t.y;
        acc[v].z = di * t.z; acc[v].w = di * t.w;
    }
    int beg = g_rowptr[warp], end = g_rowptr[warp + 1];
    for (int e = beg; e < end; e++) {
        int s = g_esrc[e];
        float w = g_dinv[s];
        #pragma unroll
        for (int v = 0; v < V; v++) {
            float4 t = x4[(size_t)s * (F / 4) + v * 32 + lane];
            acc[v].x = fmaf(w, t.x, acc[v].x);
            acc[v].y = fmaf(w, t.y, acc[v].y);
            acc[v].z = fmaf(w, t.z, acc[v].z);
            acc[v].w = fmaf(w, t.w, acc[v].w);
        }
    }
    float4* __restrict__ o4 = (float4*)out;
    #pragma unroll
    for (int v = 0; v < V; v++) {
        float4 r;
        r.x = di * acc[v].x; r.y = di * acc[v].y;
        r.z = di * acc[v].z; r.w = di * acc[v].w;
        o4[(size_t)warp * (F / 4) + v * 32 + lane] = r;
    }
}

// ---------------- tensor GEMM via mma.sync (legacy HMMA path) ----------------
// C[M,256] = relu(A[M,K] @ W[K,256] + b), bf16 3-term split, fp32 accum.
__device__ __forceinline__ void mma_bf16(float* c, const uint32_t* a, uint32_t b0, uint32_t b1) {
    asm volatile(
        "mma.sync.aligned.m16n8k16.row.col.f32.bf16.bf16.f32 "
        "{%0,%1,%2,%3}, {%4,%5,%6,%7}, {%8,%9}, {%0,%1,%2,%3};"
        : "+f"(c[0]), "+f"(c[1]), "+f"(c[2]), "+f"(c[3])
        : "r"(a[0]), "r"(a[1]), "r"(a[2]), "r"(a[3]), "r"(b0), "r"(b1));
}

#define KC 32
#define KS_STRIDE 40   // bf16 row stride (20 words): conflict-free for frag pattern

template <int K>
__global__ __launch_bounds__(256, 2)
void gemm_mma(const float* __restrict__ A, const __nv_bfloat16* __restrict__ Wh,
              const __nv_bfloat16* __restrict__ Wl, const float* __restrict__ bias,
              float* __restrict__ C, int M) {
    __shared__ __nv_bfloat16 sAh[128 * KS_STRIDE];
    __shared__ __nv_bfloat16 sAl[128 * KS_STRIDE];
    __shared__ __nv_bfloat16 sBh[128 * KS_STRIDE];
    __shared__ __nv_bfloat16 sBl[128 * KS_STRIDE];

    const int tid = threadIdx.x;
    const int wid = tid >> 5;
    const int lane = tid & 31;
    const int row0 = blockIdx.x * 128;
    const int colbase = blockIdx.y * 128;
    const int m_off = (wid & 3) * 32;   // warp rows within CTA tile
    const int n_off = (wid >> 2) * 64;  // warp cols within CTA tile

    float acc[2][8][4];
    #pragma unroll
    for (int mt = 0; mt < 2; mt++)
        #pragma unroll
        for (int nt = 0; nt < 8; nt++)
            #pragma unroll
            for (int q = 0; q < 4; q++) acc[mt][nt][q] = 0.f;

    for (int k0 = 0; k0 < K; k0 += KC) {
        // --- stage A (128 x 32 fp32 -> split bf16 h/l) ---
        #pragma unroll
        for (int it = 0; it < 4; it++) {
            int i = tid + it * 256;        // 0..1023 float4
            int r = i >> 3;                // row 0..127
            int q = (i & 7) * 4;           // k offset 0..28
            float4 v = make_float4(0.f, 0.f, 0.f, 0.f);
            if (row0 + r < M)
                v = *(const float4*)(A + (size_t)(row0 + r) * K + k0 + q);
            float hx = __bfloat162float(__float2bfloat16_rn(v.x));
            float hy = __bfloat162float(__float2bfloat16_rn(v.y));
            float hz = __bfloat162float(__float2bfloat16_rn(v.z));
            float hw = __bfloat162float(__float2bfloat16_rn(v.w));
            __nv_bfloat162* ph = (__nv_bfloat162*)(sAh + r * KS_STRIDE + q);
            __nv_bfloat162* pl = (__nv_bfloat162*)(sAl + r * KS_STRIDE + q);
            ph[0] = __floats2bfloat162_rn(hx, hy);
            ph[1] = __floats2bfloat162_rn(hz, hw);
            pl[0] = __floats2bfloat162_rn(v.x - hx, v.y - hy);
            pl[1] = __floats2bfloat162_rn(v.z - hz, v.w - hw);
        }
        // --- stage B (128 cols x 32 k, already split bf16, [n][k]) ---
        #pragma unroll
        for (int it = 0; it < 4; it++) {
            int i = tid + it * 256;        // 0..1023 (4-bf16 groups)
            int nn = i >> 3;               // col 0..127
            int q = (i & 7) * 4;           // k offset
            const uint2* gh = (const uint2*)(Wh + (size_t)(colbase + nn) * K + k0 + q);
            const uint2* gl = (const uint2*)(Wl + (size_t)(colbase + nn) * K + k0 + q);
            *(uint2*)(sBh + nn * KS_STRIDE + q) = *gh;
            *(uint2*)(sBl + nn * KS_STRIDE + q) = *gl;
        }
        __syncthreads();

        #pragma unroll
        for (int ks = 0; ks < KC; ks += 16) {
            uint32_t ah[2][4], al[2][4];
            #pragma unroll
            for (int mt = 0; mt < 2; mt++) {
                int r = m_off + mt * 16 + (lane >> 2);
                int cofs = ks + (lane & 3) * 2;
                ah[mt][0] = *(const uint32_t*)(sAh + r * KS_STRIDE + cofs);
                ah[mt][1] = *(const uint32_t*)(sAh + (r + 8) * KS_STRIDE + cofs);
                ah[mt][2] = *(const uint32_t*)(sAh + r * KS_STRIDE + cofs + 8);
                ah[mt][3] = *(const uint32_t*)(sAh + (r + 8) * KS_STRIDE + cofs + 8);
                al[mt][0] = *(const uint32_t*)(sAl + r * KS_STRIDE + cofs);
                al[mt][1] = *(const uint32_t*)(sAl + (r + 8) * KS_STRIDE + cofs);
                al[mt][2] = *(const uint32_t*)(sAl + r * KS_STRIDE + cofs + 8);
                al[mt][3] = *(const uint32_t*)(sAl + (r + 8) * KS_STRIDE + cofs + 8);
            }
            #pragma unroll
            for (int nt = 0; nt < 8; nt++) {
                int cc = n_off + nt * 8 + (lane >> 2);
                int cofs = ks + (lane & 3) * 2;
                uint32_t bh0 = *(const uint32_t*)(sBh + cc * KS_STRIDE + cofs);
                uint32_t bh1 = *(const uint32_t*)(sBh + cc * KS_STRIDE + cofs + 8);
                uint32_t bl0 = *(const uint32_t*)(sBl + cc * KS_STRIDE + cofs);
                uint32_t bl1 = *(const uint32_t*)(sBl + cc * KS_STRIDE + cofs + 8);
                #pragma unroll
                for (int mt = 0; mt < 2; mt++) {
                    mma_bf16(acc[mt][nt], ah[mt], bh0, bh1);
                    mma_bf16(acc[mt][nt], al[mt], bh0, bh1);
                    mma_bf16(acc[mt][nt], ah[mt], bl0, bl1);
                }
            }
        }
        __syncthreads();
    }

    // --- epilogue: bias + relu + store ---
    #pragma unroll
    for (int mt = 0; mt < 2; mt++) {
        int row = row0 + m_off + mt * 16 + (lane >> 2);
        #pragma unroll
        for (int nt = 0; nt < 8; nt++) {
            int col = colbase + n_off + nt * 8 + (lane & 3) * 2;
            float b0 = bias[col], b1 = bias[col + 1];
            if (row < M) {
                float2 o;
                o.x = acc[mt][nt][0] + b0; o.y = acc[mt][nt][1] + b1;
                o.x = o.x > 0.f ? o.x : 0.f;
                o.y = o.y > 0.f ? o.y : 0.f;
                *(float2*)(C + (size_t)row * 256 + col) = o;
            }
            if (row + 8 < M) {
                float2 o;
                o.x = acc[mt][nt][2] + b0; o.y = acc[mt][nt][3] + b1;
                o.x = o.x > 0.f ? o.x : 0.f;
                o.y = o.y > 0.f ? o.y : 0.f;
                *(float2*)(C + (size_t)(row + 8) * 256 + col) = o;
            }
        }
    }
}

// ---------------- pooling + heads ----------------
__device__ __forceinline__ int lower_bound_i(const int* __restrict__ a, int n, int key) {
    int lo = 0, hi = n;
    while (lo < hi) {
        int mid = (lo + hi) >> 1;
        if (a[mid] < key) lo = mid + 1; else hi = mid;
    }
    return lo;
}
__global__ __launch_bounds__(256)
void pool_heads_kernel(const float* __restrict__ h, const int* __restrict__ batch,
                       const float* __restrict__ Wmu, const float* __restrict__ bmu,
                       const float* __restrict__ Wlv, const float* __restrict__ blv,
                       float* __restrict__ out, int n, int g_total) {
    int g = blockIdx.x;
    __shared__ float hg[256];
    int lo = lower_bound_i(batch, n, g);
    int hi = lower_bound_i(batch, n, g + 1);
    int tid = threadIdx.x;
    float s = 0.f;
    for (int i = lo; i < hi; i++) s += h[(size_t)i * 256 + tid];
    float cnt = (float)(hi - lo);
    hg[tid] = s / fmaxf(cnt, 1.0f);
    __syncthreads();
    if (tid < 64) {
        float m = bmu[tid];
        #pragma unroll 8
        for (int k = 0; k < 256; k++) m = fmaf(hg[k], Wmu[k * 64 + tid], m);
        out[g * 64 + tid] = m;
    } else if (tid < 128) {
        int t = tid - 64;
        float m = blv[t];
        #pragma unroll 8
        for (int k = 0; k < 256; k++) m = fmaf(hg[k], Wlv[k * 64 + t], m);
        out[(size_t)g_total * 64 + g * 64 + t] = m;
    }
}

// ---------------- launch ----------------
extern "C" void kernel_launch(void* const* d_in, const int* in_sizes, int n_in,
                              void* d_out, int out_size) {
    const float* x     = (const float*)d_in[0];
    const int*   ei    = (const int*)d_in[1];
    const int*   batch = (const int*)d_in[2];
    int wi = (n_in >= 12) ? 4 : 3;
    const float* W1  = (const float*)d_in[wi + 0];
    const float* b1  = (const float*)d_in[wi + 1];
    const float* W2  = (const float*)d_in[wi + 2];
    const float* b2  = (const float*)d_in[wi + 3];
    const float* Wmu = (const float*)d_in[wi + 4];
    const float* bmu = (const float*)d_in[wi + 5];
    const float* Wlv = (const float*)d_in[wi + 6];
    const float* blv = (const float*)d_in[wi + 7];
    float* out = (float*)d_out;

    int n = in_sizes[0] / 128;
    int e = in_sizes[1] / 2;
    int g = out_size / 128;

    static float* p_agg = nullptr;
    static float* p_h = nullptr;
    static __nv_bfloat16* p_w1h = nullptr; static __nv_bfloat16* p_w1l = nullptr;
    static __nv_bfloat16* p_w2h = nullptr; static __nv_bfloat16* p_w2l = nullptr;
    if (!p_agg) {
        cudaGetSymbolAddress((void**)&p_agg, g_agg);
        cudaGetSymbolAddress((void**)&p_h, g_h);
        cudaGetSymbolAddress((void**)&p_w1h, g_W1h);
        cudaGetSymbolAddress((void**)&p_w1l, g_W1l);
        cudaGetSymbolAddress((void**)&p_w2h, g_W2h);
        cudaGetSymbolAddress((void**)&p_w2l, g_W2l);
    }

    zero_deg_kernel<<<(n + 255) / 256, 256>>>(n);
    hist_kernel<<<(e + 255) / 256, 256>>>(ei, e);
    scan_kernel<<<1, 1024>>>(n);
    fill_kernel<<<(e + 255) / 256, 256>>>(ei, e);
    prep_w_kernel<128><<<(256 * 128 + 255) / 256, 256>>>(W1, p_w1h, p_w1l);
    prep_w_kernel<256><<<(256 * 256 + 255) / 256, 256>>>(W2, p_w2h, p_w2l);

    agg_kernel<128><<<(n + 7) / 8, 256>>>(x, p_agg, n);
    gemm_mma<128><<<dim3((n + 127) / 128, 2), 256>>>(p_agg, p_w1h, p_w1l, b1, p_h, n);
    agg_kernel<256><<<(n + 7) / 8, 256>>>(p_h, p_agg, n);
    gemm_mma<256><<<dim3((n + 127) / 128, 2), 256>>>(p_agg, p_w2h, p_w2l, b2, p_h, n);
    pool_heads_kernel<<<g, 256>>>(p_h, batch, Wmu, bmu, Wlv, blv, out, n, g);
}